// round 15
// baseline (speedup 1.0000x reference)
#include <cuda_runtime.h>
#include <cstdint>

#define NBATCH 16
#define NA 128
#define HD 256
#define EF 30

#define SELU_SCALE 1.0507009873554805f
#define SELU_SA    1.7580993408473766f     // scale * alpha
#define LOG2E      1.4426950408889634f
#define SLN2       (1.0507009873554805f * 0.69314718055994531f)  // scale*ln2
#define SA_H2      0x3F083F08u             // f16x2 {1.7578125, 1.7578125}
#define NSA_H2     0xBF08BF08u             // f16x2 {-1.7578125, -1.7578125}

// intermediate h1 (16*128*256 fp32 = 2 MB)
__device__ float g_h1[NBATCH * NA * HD];

__device__ __forceinline__ uint32_t f2tf(float x) {
    uint32_t u; asm("cvt.rna.tf32.f32 %0, %1;" : "=r"(u) : "f"(x)); return u;
}
__device__ __forceinline__ float ex2f(float x) {
    float y; asm("ex2.approx.f32 %0, %1;" : "=f"(y) : "f"(x)); return y;
}
// scalar selu on d2 = d*log2e (for k2 epilogue)
__device__ __forceinline__ float selu_l2(float d2) {
    float e = ex2f(d2);
    return fmaf(SLN2, fmaxf(d2, 0.f), fminf(fmaf(SELU_SA, e, -SELU_SA), 0.f));
}
__device__ __forceinline__ unsigned long long pack2(float a, float b) {
    unsigned long long v;
    asm("mov.b64 %0, {%1, %2};" : "=l"(v) : "f"(a), "f"(b));
    return v;
}
__device__ __forceinline__ unsigned long long mul2(unsigned long long a,
                                                   unsigned long long b) {
    unsigned long long d;
    asm("mul.rn.f32x2 %0, %1, %2;" : "=l"(d) : "l"(a), "l"(b));
    return d;
}
__device__ __forceinline__ unsigned long long fma2(unsigned long long a,
                                                   unsigned long long b,
                                                   unsigned long long c) {
    unsigned long long d;
    asm("fma.rn.f32x2 %0, %1, %2, %3;" : "=l"(d) : "l"(a), "l"(b), "l"(c));
    return d;
}
__device__ __forceinline__ void unpack2(unsigned long long v, float& a, float& b) {
    asm("mov.b64 {%0, %1}, %2;" : "=f"(a), "=f"(b) : "l"(v));
}
// packed selu pair on (c0,c1) = d*log2e -> f32x2 {selu(d0), selu(d1)}
__device__ __forceinline__ unsigned long long selu2(float c0, float c1) {
    uint32_t h2, e2, f2, n2;
    asm("cvt.rn.f16x2.f32 %0, %1, %2;" : "=r"(h2) : "f"(c1), "f"(c0)); // lo=c0
    asm("ex2.approx.f16x2 %0, %1;" : "=r"(e2) : "r"(h2));
    asm("fma.rn.f16x2 %0, %1, %2, %3;"
        : "=r"(f2) : "r"(e2), "r"(SA_H2), "r"(NSA_H2));
    asm("min.f16x2 %0, %1, %2;" : "=r"(n2) : "r"(f2), "r"(0u));
    float n0, n1;
    asm("{ .reg .b16 lo, hi;\n\t"
        "mov.b32 {lo, hi}, %2;\n\t"
        "cvt.f32.f16 %0, lo;\n\t"
        "cvt.f32.f16 %1, hi; }"
        : "=f"(n0), "=f"(n1) : "r"(n2));
    float s0 = fmaf(SLN2, fmaxf(c0, 0.f), n0);
    float s1 = fmaf(SLN2, fmaxf(c1, 0.f), n1);
    return pack2(s0, s1);
}
__device__ __forceinline__ void mma_tf32(float c[4],
                                         uint32_t a0, uint32_t a1, uint32_t a2, uint32_t a3,
                                         uint32_t b0, uint32_t b1) {
    asm volatile(
        "mma.sync.aligned.m16n8k8.row.col.f32.tf32.tf32.f32 "
        "{%0,%1,%2,%3}, {%4,%5,%6,%7}, {%8,%9}, {%0,%1,%2,%3};"
        : "+f"(c[0]), "+f"(c[1]), "+f"(c[2]), "+f"(c[3])
        : "r"(a0), "r"(a1), "r"(a2), "r"(a3), "r"(b0), "r"(b1));
}
__device__ __forceinline__ uint32_t smem_u32(const void* p) {
    return (uint32_t)__cvta_generic_to_shared(p);
}
#define CP_ASYNC16(dst_u32, src) \
    asm volatile("cp.async.ca.shared.global [%0], [%1], 16;" \
                 :: "r"(dst_u32), "l"(src))
#define CP_COMMIT() asm volatile("cp.async.commit_group;" ::: "memory")
#define CP_WAIT0()  asm volatile("cp.async.wait_group 0;" ::: "memory")

// =========================================================================
// Kernel 1 (unchanged from R14 best): CTA = (b, i-tile of 4, f-half).
// grid = 1024, launch_bounds(256,3). Double-buffered; cp.async h staging;
// fragment-order A; packed f16x2 selu epilogue; lane-pair fold.
// =========================================================================
#define EMS 132
#define K1_AFW (16 * 132)
#define K1_HW  (16 * 128)

__global__ __launch_bounds__(256, 3) void efconv_k1(
    const float* __restrict__ hbuf, const float* __restrict__ e,
    const float* __restrict__ edge_mask, const float* __restrict__ Wf,
    const float* __restrict__ bf)
{
    __shared__ uint32_t afb[2][K1_AFW];
    __shared__ float    hqb[2][K1_HW];
    __shared__ float    em_s[4 * EMS];

    const int tid = threadIdx.x;
    const int w = tid >> 5, l = tid & 31;
    const int r = l >> 2, c = l & 3;
    const int bid = blockIdx.x;
    const int fh = bid & 1, it = (bid >> 1) & 31, b = bid >> 6;
    const int i0 = it * 4;
    const int f0w = fh * 128 + w * 16;
    const int flw = w * 16;

    const int h_jj0 = tid >> 5, h_fq0 = tid & 31;
    const int h_jj1 = (tid + 256) >> 5, h_fq1 = tid & 31;

    uint32_t B[4][2][2];
    float2 bfv[2];
    #pragma unroll
    for (int nb = 0; nb < 2; nb++) {
        const int fr = f0w + nb * 8 + r;
        #pragma unroll
        for (int ks = 0; ks < 4; ks++) {
            int k0 = ks * 8 + c, k1 = k0 + 4;
            B[ks][nb][0] = f2tf(Wf[fr * EF + k0] * LOG2E);
            B[ks][nb][1] = (k1 < EF) ? f2tf(Wf[fr * EF + k1] * LOG2E) : 0u;
        }
        float2 bv = *(const float2*)(bf + f0w + nb * 8 + 2 * c);
        bfv[nb] = make_float2(bv.x * LOG2E, bv.y * LOG2E);
    }

    #pragma unroll
    for (int q = 0; q < 2; q++) {
        int idx = tid + q * 256;
        int i_l = idx >> 7, j = idx & 127;
        em_s[i_l * EMS + j] = edge_mask[((b * NA) + i0 + i_l) * NA + j];
    }
    if (tid < 64) {
        int rr = tid, t = rr >> 4, rloc = rr & 15;
        int rbit = rloc >> 3, r8 = rloc & 7;
        int base = (t * 4 + 3) * 132 + r8 * 16;
        #pragma unroll
        for (int bu = 0; bu < 2; bu++) {
            afb[bu][base + 2 * 4 + (rbit | 2)] = 0u;
            afb[bu][base + 3 * 4 + (rbit | 2)] = 0u;
        }
    }

    {
        CP_ASYNC16(smem_u32(hqb[0] + h_jj0 * 128 + h_fq0 * 4),
                   hbuf + (size_t)(b * NA + h_jj0) * HD + fh * 128 + h_fq0 * 4);
        CP_ASYNC16(smem_u32(hqb[0] + h_jj1 * 128 + h_fq1 * 4),
                   hbuf + (size_t)(b * NA + h_jj1) * HD + fh * 128 + h_fq1 * 4);
        CP_COMMIT();
        #pragma unroll
        for (int q = 0; q < 4; q++) {
            int idx = tid + q * 256;
            if (idx < 960) {
                int i_l = idx / 240, rem = idx - i_l * 240;
                int jj = rem / 15, p = rem - jj * 15;
                float2 v = *(const float2*)(
                    e + ((size_t)((b * NA + i0 + i_l) * NA) + jj) * EF + 2 * p);
                int rr = jj * 4 + i_l;
                int t = rr >> 4, rloc = rr & 15;
                int rbit = rloc >> 3, r8 = rloc & 7;
                int ks = p >> 2, kin = (2 * p) & 7;
                int c0 = kin & 3, chalf = kin >> 2;
                int slot = (t * 4 + ks) * 132 + (r8 * 4 + c0) * 4 + (rbit | (chalf << 1));
                afb[0][slot]     = f2tf(v.x);
                afb[0][slot + 4] = f2tf(v.y);
            }
        }
        CP_WAIT0();
    }
    __syncthreads();

    unsigned long long acc2[2] = {};

    #pragma unroll 1
    for (int jt = 0; jt < 8; jt++) {
        const int buf = jt & 1;

        float2 va[4];
        if (jt < 7) {
            const int jn = (jt + 1) * 16;
            CP_ASYNC16(smem_u32(hqb[buf ^ 1] + h_jj0 * 128 + h_fq0 * 4),
                       hbuf + (size_t)(b * NA + jn + h_jj0) * HD + fh * 128 + h_fq0 * 4);
            CP_ASYNC16(smem_u32(hqb[buf ^ 1] + h_jj1 * 128 + h_fq1 * 4),
                       hbuf + (size_t)(b * NA + jn + h_jj1) * HD + fh * 128 + h_fq1 * 4);
            CP_COMMIT();
            #pragma unroll
            for (int q = 0; q < 4; q++) {
                int idx = tid + q * 256;
                if (idx < 960) {
                    int i_l = idx / 240, rem = idx - i_l * 240;
                    int jj = rem / 15, p = rem - jj * 15;
                    va[q] = *(const float2*)(
                        e + ((size_t)((b * NA + i0 + i_l) * NA) + jn + jj) * EF + 2 * p);
                }
            }
        }

        const uint32_t* af = afb[buf];
        const float*    hq = hqb[buf];

        #pragma unroll
        for (int t = 0; t < 4; t++) {
            const int qa = r >> 2;
            const float em0 = em_s[(r & 3) * EMS + jt * 16 + t * 4 + qa];
            const float em1 = em_s[(r & 3) * EMS + jt * 16 + t * 4 + qa + 2];
            const unsigned long long em0p = pack2(em0, em0);
            const unsigned long long em1p = pack2(em1, em1);
            float C[2][4];
            #pragma unroll
            for (int nb = 0; nb < 2; nb++) {
                C[nb][0] = bfv[nb].x; C[nb][1] = bfv[nb].y;
                C[nb][2] = bfv[nb].x; C[nb][3] = bfv[nb].y;
            }
            #pragma unroll
            for (int ks = 0; ks < 4; ks++) {
                uint4 av = *(const uint4*)(af + (t * 4 + ks) * 132 + l * 4);
                mma_tf32(C[0], av.x, av.y, av.z, av.w, B[ks][0][0], B[ks][0][1]);
                mma_tf32(C[1], av.x, av.y, av.z, av.w, B[ks][1][0], B[ks][1][1]);
            }
            #pragma unroll
            for (int nb = 0; nb < 2; nb++) {
                const int fl = flw + nb * 8 + 2 * c;
                unsigned long long h0 =
                    *(const unsigned long long*)(hq + (t * 4 + qa) * 128 + fl);
                unsigned long long h1 =
                    *(const unsigned long long*)(hq + (t * 4 + qa + 2) * 128 + fl);
                unsigned long long s01 = mul2(selu2(C[nb][0], C[nb][1]), em0p);
                unsigned long long s23 = mul2(selu2(C[nb][2], C[nb][3]), em1p);
                acc2[nb] = fma2(s01, h0, acc2[nb]);
                acc2[nb] = fma2(s23, h1, acc2[nb]);
            }
        }

        if (jt < 7) {
            uint32_t* af1 = afb[buf ^ 1];
            #pragma unroll
            for (int q = 0; q < 4; q++) {
                int idx = tid + q * 256;
                if (idx < 960) {
                    int i_l = idx / 240, rem = idx - i_l * 240;
                    int jj = rem / 15, p = rem - jj * 15;
                    int rr = jj * 4 + i_l;
                    int t = rr >> 4, rloc = rr & 15;
                    int rbit = rloc >> 3, r8 = rloc & 7;
                    int ks = p >> 2, kin = (2 * p) & 7;
                    int c0 = kin & 3, chalf = kin >> 2;
                    int slot = (t * 4 + ks) * 132 + (r8 * 4 + c0) * 4 + (rbit | (chalf << 1));
                    af1[slot]     = f2tf(va[q].x);
                    af1[slot + 4] = f2tf(va[q].y);
                }
            }
            CP_WAIT0();
            __syncthreads();
        }
    }

    #pragma unroll
    for (int nb = 0; nb < 2; nb++) {
        float a0, a1; unpack2(acc2[nb], a0, a1);
        a0 += __shfl_xor_sync(0xffffffffu, a0, 16);
        a1 += __shfl_xor_sync(0xffffffffu, a1, 16);
        if (l < 16) {
            const int f = f0w + nb * 8 + 2 * c;
            *(float2*)(g_h1 + (size_t)(b * NA + i0 + r) * HD + f) = make_float2(a0, a1);
        }
    }
}

// =========================================================================
// Kernel 2 (retiled): out = selu([h|h1] @ Ww^T + bw) * nm + h
// M=2048, K=512, N=256. Grid 512 = 128 rb x 4 fb; CTA = 16 rows x 64 f.
// 8 warps: warp w covers 8 f (fh = w, nb eliminated); one m16 row tile.
// smem 41.5 KB (both buffers) -> 3.46 CTAs/SM resident = ~28 warps/SM.
// LDG-early/STS-late double-buffered K-chunks of 64. Fragment-order smem.
// =========================================================================
#define K2_ZW (8 * 132)
#define K2_WW (8 * 516)
#define K2_SMEM ((2*(K2_ZW + K2_WW)) * 4)

__global__ __launch_bounds__(256) void efconv_k2(
    const float* __restrict__ hbuf, const float* __restrict__ node_mask,
    const float* __restrict__ Ww, const float* __restrict__ bw,
    float* __restrict__ out)
{
    extern __shared__ uint32_t sm2[];
    uint32_t* zfb[2] = { sm2, sm2 + K2_ZW };
    uint32_t* wfb[2] = { sm2 + 2 * K2_ZW, sm2 + 2 * K2_ZW + K2_WW };

    const int tid = threadIdx.x;
    const int w = tid >> 5, l = tid & 31;
    const int r = l >> 2, c = l & 3;
    const int rb = blockIdx.x >> 2, fb = blockIdx.x & 3;
    const int row0 = rb * 16;
    const int fh = w;                       // warp's 8-f slice

    float C[4];
    {
        float2 bv = *(const float2*)(bw + fb * 64 + fh * 8 + 2 * c);
        C[0] = bv.x * LOG2E; C[1] = bv.y * LOG2E;
        C[2] = bv.x * LOG2E; C[3] = bv.y * LOG2E;
    }

    // ---- prologue: stage kc = 0 ----
    {
        // z: 16 rows x 64 k = 256 float4, 1 per thread
        {
            int rr = tid >> 4, kq = tid & 15;
            float4 v = *(const float4*)(hbuf + (size_t)(row0 + rr) * HD + kq * 4);
            int rbit = rr >> 3, r8 = rr & 7;
            int ks = kq >> 1, chalf = kq & 1;
            uint32_t* d = zfb[0] + ks * 132 + r8 * 16 + (rbit | (chalf << 1));
            d[0] = f2tf(v.x); d[4] = f2tf(v.y);
            d[8] = f2tf(v.z); d[12] = f2tf(v.w);
        }
        // Ww: 64 f x 64 k = 1024 float4, 4 per thread
        #pragma unroll
        for (int q = 0; q < 4; q++) {
            int idx = tid + q * 256;
            int ff = idx >> 4, kq = idx & 15;
            float4 v = *(const float4*)(Ww + (size_t)(fb * 64 + ff) * (2 * HD) + kq * 4);
            int ks = kq >> 1, half = kq & 1;
            uint32_t* d = wfb[0] + ks * 516 + ff * 8 + half;
            d[0] = f2tf(v.x * LOG2E); d[2] = f2tf(v.y * LOG2E);
            d[4] = f2tf(v.z * LOG2E); d[6] = f2tf(v.w * LOG2E);
        }
    }
    __syncthreads();

    #pragma unroll 1
    for (int kc = 0; kc < 8; kc++) {
        const int buf = kc & 1;

        // ---- prefetch stage kc+1 (LDG only) ----
        float4 zv, wv[4];
        if (kc < 7) {
            const float* zsrc = (kc + 1 < 4) ? hbuf : g_h1;
            const int cb = ((kc + 1) & 3) * 64;
            {
                int rr = tid >> 4, kq = tid & 15;
                zv = *(const float4*)(zsrc + (size_t)(row0 + rr) * HD + cb + kq * 4);
            }
            #pragma unroll
            for (int q = 0; q < 4; q++) {
                int idx = tid + q * 256;
                int ff = idx >> 4, kq = idx & 15;
                wv[q] = *(const float4*)(
                    Ww + (size_t)(fb * 64 + ff) * (2 * HD) + (kc + 1) * 64 + kq * 4);
            }
        }

        // ---- compute stage kc ----
        const uint32_t* zf = zfb[buf];
        const uint32_t* wf = wfb[buf];
        #pragma unroll
        for (int ks = 0; ks < 8; ks++) {
            uint4 av = *(const uint4*)(zf + ks * 132 + l * 4);
            uint2 bb = *(const uint2*)(wf + ks * 516 + (fh * 8 + r) * 8 + c * 2);
            mma_tf32(C, av.x, av.y, av.z, av.w, bb.x, bb.y);
        }

        // ---- STS stage kc+1 + barrier ----
        if (kc < 7) {
            uint32_t* zf1 = zfb[buf ^ 1];
            uint32_t* wf1 = wfb[buf ^ 1];
            {
                int rr = tid >> 4, kq = tid & 15;
                int rbit = rr >> 3, r8 = rr & 7;
                int ks = kq >> 1, chalf = kq & 1;
                uint32_t* d = zf1 + ks * 132 + r8 * 16 + (rbit | (chalf << 1));
                d[0] = f2tf(zv.x); d[4] = f2tf(zv.y);
                d[8] = f2tf(zv.z); d[12] = f2tf(zv.w);
            }
            #pragma unroll
            for (int q = 0; q < 4; q++) {
                int idx = tid + q * 256;
                int ff = idx >> 4, kq = idx & 15;
                int ks = kq >> 1, half = kq & 1;
                uint32_t* d = wf1 + ks * 516 + ff * 8 + half;
                d[0] = f2tf(wv[q].x * LOG2E); d[2] = f2tf(wv[q].y * LOG2E);
                d[4] = f2tf(wv[q].z * LOG2E); d[6] = f2tf(wv[q].w * LOG2E);
            }
            __syncthreads();
        }
    }

    // ---- epilogue: selu(D) * nm + h  (C = d*log2e) ----
    const int rg0 = row0 + r, rg1 = rg0 + 8;
    const float nm0 = node_mask[rg0], nm1 = node_mask[rg1];
    const int f = fb * 64 + fh * 8 + 2 * c;
    float2 h0 = *(const float2*)(hbuf + (size_t)rg0 * HD + f);
    float2 h1 = *(const float2*)(hbuf + (size_t)rg1 * HD + f);
    float2 o0, o1;
    o0.x = selu_l2(C[0]) * nm0 + h0.x;
    o0.y = selu_l2(C[1]) * nm0 + h0.y;
    o1.x = selu_l2(C[2]) * nm1 + h1.x;
    o1.y = selu_l2(C[3]) * nm1 + h1.y;
    *(float2*)(out + (size_t)rg0 * HD + f) = o0;
    *(float2*)(out + (size_t)rg1 * HD + f) = o1;
}

extern "C" void kernel_launch(void* const* d_in, const int* in_sizes, int n_in,
                              void* d_out, int out_size)
{
    const float* h   = (const float*)d_in[0];   // (16,128,256)
    const float* e   = (const float*)d_in[1];   // (16,128,128,30)
    const float* nm  = (const float*)d_in[2];   // (16,128,1)
    const float* em  = (const float*)d_in[3];   // (16,128,128,1)
    const float* Wf  = (const float*)d_in[4];   // (256,30)
    const float* bf  = (const float*)d_in[5];   // (256,)
    const float* Ww  = (const float*)d_in[6];   // (256,512)
    const float* bw  = (const float*)d_in[7];   // (256,)
    float* out = (float*)d_out;                  // (16,128,256)

    cudaFuncSetAttribute(efconv_k2, cudaFuncAttributeMaxDynamicSharedMemorySize, K2_SMEM);

    efconv_k1<<<1024, 256>>>(h, e, em, Wf, bf);
    efconv_k2<<<512, 256, K2_SMEM>>>(h, nm, Ww, bw, out);
}

// round 16
// speedup vs baseline: 1.1031x; 1.1031x over previous
#include <cuda_runtime.h>
#include <cstdint>

#define NBATCH 16
#define NA 128
#define HD 256
#define EF 30

#define SELU_SCALE 1.0507009873554805f
#define SELU_SA    1.7580993408473766f     // scale * alpha
#define LOG2E      1.4426950408889634f
#define SLN2       (1.0507009873554805f * 0.69314718055994531f)  // scale*ln2
#define SA_H2      0x3F083F08u             // f16x2 {1.7578125, 1.7578125}
#define NSA_H2     0xBF08BF08u             // f16x2 {-1.7578125, -1.7578125}

// intermediate h1 (16*128*256 fp32 = 2 MB)
__device__ float g_h1[NBATCH * NA * HD];

__device__ __forceinline__ uint32_t f2tf(float x) {
    uint32_t u; asm("cvt.rna.tf32.f32 %0, %1;" : "=r"(u) : "f"(x)); return u;
}
__device__ __forceinline__ float ex2f(float x) {
    float y; asm("ex2.approx.f32 %0, %1;" : "=f"(y) : "f"(x)); return y;
}
// scalar selu on d2 = d*log2e (for k2 epilogue)
__device__ __forceinline__ float selu_l2(float d2) {
    float e = ex2f(d2);
    return fmaf(SLN2, fmaxf(d2, 0.f), fminf(fmaf(SELU_SA, e, -SELU_SA), 0.f));
}
__device__ __forceinline__ unsigned long long pack2(float a, float b) {
    unsigned long long v;
    asm("mov.b64 %0, {%1, %2};" : "=l"(v) : "f"(a), "f"(b));
    return v;
}
__device__ __forceinline__ unsigned long long mul2(unsigned long long a,
                                                   unsigned long long b) {
    unsigned long long d;
    asm("mul.rn.f32x2 %0, %1, %2;" : "=l"(d) : "l"(a), "l"(b));
    return d;
}
__device__ __forceinline__ unsigned long long fma2(unsigned long long a,
                                                   unsigned long long b,
                                                   unsigned long long c) {
    unsigned long long d;
    asm("fma.rn.f32x2 %0, %1, %2, %3;" : "=l"(d) : "l"(a), "l"(b), "l"(c));
    return d;
}
__device__ __forceinline__ void unpack2(unsigned long long v, float& a, float& b) {
    asm("mov.b64 {%0, %1}, %2;" : "=f"(a), "=f"(b) : "l"(v));
}
// packed selu pair on (c0,c1) = d*log2e -> f32x2 {selu(d0), selu(d1)}
__device__ __forceinline__ unsigned long long selu2(float c0, float c1) {
    uint32_t h2, e2, f2, n2;
    asm("cvt.rn.f16x2.f32 %0, %1, %2;" : "=r"(h2) : "f"(c1), "f"(c0)); // lo=c0
    asm("ex2.approx.f16x2 %0, %1;" : "=r"(e2) : "r"(h2));
    asm("fma.rn.f16x2 %0, %1, %2, %3;"
        : "=r"(f2) : "r"(e2), "r"(SA_H2), "r"(NSA_H2));
    asm("min.f16x2 %0, %1, %2;" : "=r"(n2) : "r"(f2), "r"(0u));
    float n0, n1;
    asm("{ .reg .b16 lo, hi;\n\t"
        "mov.b32 {lo, hi}, %2;\n\t"
        "cvt.f32.f16 %0, lo;\n\t"
        "cvt.f32.f16 %1, hi; }"
        : "=f"(n0), "=f"(n1) : "r"(n2));
    float s0 = fmaf(SLN2, fmaxf(c0, 0.f), n0);
    float s1 = fmaf(SLN2, fmaxf(c1, 0.f), n1);
    return pack2(s0, s1);
}
__device__ __forceinline__ void mma_tf32(float c[4],
                                         uint32_t a0, uint32_t a1, uint32_t a2, uint32_t a3,
                                         uint32_t b0, uint32_t b1) {
    asm volatile(
        "mma.sync.aligned.m16n8k8.row.col.f32.tf32.tf32.f32 "
        "{%0,%1,%2,%3}, {%4,%5,%6,%7}, {%8,%9}, {%0,%1,%2,%3};"
        : "+f"(c[0]), "+f"(c[1]), "+f"(c[2]), "+f"(c[3])
        : "r"(a0), "r"(a1), "r"(a2), "r"(a3), "r"(b0), "r"(b1));
}
__device__ __forceinline__ uint32_t smem_u32(const void* p) {
    return (uint32_t)__cvta_generic_to_shared(p);
}
#define CP_ASYNC16(dst_u32, src) \
    asm volatile("cp.async.ca.shared.global [%0], [%1], 16;" \
                 :: "r"(dst_u32), "l"(src))
#define CP_COMMIT() asm volatile("cp.async.commit_group;" ::: "memory")
#define CP_WAIT0()  asm volatile("cp.async.wait_group 0;" ::: "memory")

// =========================================================================
// Kernel 1 (unchanged from R14 best): CTA = (b, i-tile of 4, f-half).
// grid = 1024, launch_bounds(256,3). Double-buffered; cp.async h staging;
// fragment-order A; packed f16x2 selu epilogue; lane-pair fold.
// =========================================================================
#define EMS 132
#define K1_AFW (16 * 132)
#define K1_HW  (16 * 128)

__global__ __launch_bounds__(256, 3) void efconv_k1(
    const float* __restrict__ hbuf, const float* __restrict__ e,
    const float* __restrict__ edge_mask, const float* __restrict__ Wf,
    const float* __restrict__ bf)
{
    __shared__ uint32_t afb[2][K1_AFW];
    __shared__ float    hqb[2][K1_HW];
    __shared__ float    em_s[4 * EMS];

    const int tid = threadIdx.x;
    const int w = tid >> 5, l = tid & 31;
    const int r = l >> 2, c = l & 3;
    const int bid = blockIdx.x;
    const int fh = bid & 1, it = (bid >> 1) & 31, b = bid >> 6;
    const int i0 = it * 4;
    const int f0w = fh * 128 + w * 16;
    const int flw = w * 16;

    const int h_jj0 = tid >> 5, h_fq0 = tid & 31;
    const int h_jj1 = (tid + 256) >> 5, h_fq1 = tid & 31;

    uint32_t B[4][2][2];
    float2 bfv[2];
    #pragma unroll
    for (int nb = 0; nb < 2; nb++) {
        const int fr = f0w + nb * 8 + r;
        #pragma unroll
        for (int ks = 0; ks < 4; ks++) {
            int k0 = ks * 8 + c, k1 = k0 + 4;
            B[ks][nb][0] = f2tf(Wf[fr * EF + k0] * LOG2E);
            B[ks][nb][1] = (k1 < EF) ? f2tf(Wf[fr * EF + k1] * LOG2E) : 0u;
        }
        float2 bv = *(const float2*)(bf + f0w + nb * 8 + 2 * c);
        bfv[nb] = make_float2(bv.x * LOG2E, bv.y * LOG2E);
    }

    #pragma unroll
    for (int q = 0; q < 2; q++) {
        int idx = tid + q * 256;
        int i_l = idx >> 7, j = idx & 127;
        em_s[i_l * EMS + j] = edge_mask[((b * NA) + i0 + i_l) * NA + j];
    }
    if (tid < 64) {
        int rr = tid, t = rr >> 4, rloc = rr & 15;
        int rbit = rloc >> 3, r8 = rloc & 7;
        int base = (t * 4 + 3) * 132 + r8 * 16;
        #pragma unroll
        for (int bu = 0; bu < 2; bu++) {
            afb[bu][base + 2 * 4 + (rbit | 2)] = 0u;
            afb[bu][base + 3 * 4 + (rbit | 2)] = 0u;
        }
    }

    {
        CP_ASYNC16(smem_u32(hqb[0] + h_jj0 * 128 + h_fq0 * 4),
                   hbuf + (size_t)(b * NA + h_jj0) * HD + fh * 128 + h_fq0 * 4);
        CP_ASYNC16(smem_u32(hqb[0] + h_jj1 * 128 + h_fq1 * 4),
                   hbuf + (size_t)(b * NA + h_jj1) * HD + fh * 128 + h_fq1 * 4);
        CP_COMMIT();
        #pragma unroll
        for (int q = 0; q < 4; q++) {
            int idx = tid + q * 256;
            if (idx < 960) {
                int i_l = idx / 240, rem = idx - i_l * 240;
                int jj = rem / 15, p = rem - jj * 15;
                float2 v = *(const float2*)(
                    e + ((size_t)((b * NA + i0 + i_l) * NA) + jj) * EF + 2 * p);
                int rr = jj * 4 + i_l;
                int t = rr >> 4, rloc = rr & 15;
                int rbit = rloc >> 3, r8 = rloc & 7;
                int ks = p >> 2, kin = (2 * p) & 7;
                int c0 = kin & 3, chalf = kin >> 2;
                int slot = (t * 4 + ks) * 132 + (r8 * 4 + c0) * 4 + (rbit | (chalf << 1));
                afb[0][slot]     = f2tf(v.x);
                afb[0][slot + 4] = f2tf(v.y);
            }
        }
        CP_WAIT0();
    }
    __syncthreads();

    unsigned long long acc2[2] = {};

    #pragma unroll 1
    for (int jt = 0; jt < 8; jt++) {
        const int buf = jt & 1;

        float2 va[4];
        if (jt < 7) {
            const int jn = (jt + 1) * 16;
            CP_ASYNC16(smem_u32(hqb[buf ^ 1] + h_jj0 * 128 + h_fq0 * 4),
                       hbuf + (size_t)(b * NA + jn + h_jj0) * HD + fh * 128 + h_fq0 * 4);
            CP_ASYNC16(smem_u32(hqb[buf ^ 1] + h_jj1 * 128 + h_fq1 * 4),
                       hbuf + (size_t)(b * NA + jn + h_jj1) * HD + fh * 128 + h_fq1 * 4);
            CP_COMMIT();
            #pragma unroll
            for (int q = 0; q < 4; q++) {
                int idx = tid + q * 256;
                if (idx < 960) {
                    int i_l = idx / 240, rem = idx - i_l * 240;
                    int jj = rem / 15, p = rem - jj * 15;
                    va[q] = *(const float2*)(
                        e + ((size_t)((b * NA + i0 + i_l) * NA) + jn + jj) * EF + 2 * p);
                }
            }
        }

        const uint32_t* af = afb[buf];
        const float*    hq = hqb[buf];

        #pragma unroll
        for (int t = 0; t < 4; t++) {
            const int qa = r >> 2;
            const float em0 = em_s[(r & 3) * EMS + jt * 16 + t * 4 + qa];
            const float em1 = em_s[(r & 3) * EMS + jt * 16 + t * 4 + qa + 2];
            const unsigned long long em0p = pack2(em0, em0);
            const unsigned long long em1p = pack2(em1, em1);
            float C[2][4];
            #pragma unroll
            for (int nb = 0; nb < 2; nb++) {
                C[nb][0] = bfv[nb].x; C[nb][1] = bfv[nb].y;
                C[nb][2] = bfv[nb].x; C[nb][3] = bfv[nb].y;
            }
            #pragma unroll
            for (int ks = 0; ks < 4; ks++) {
                uint4 av = *(const uint4*)(af + (t * 4 + ks) * 132 + l * 4);
                mma_tf32(C[0], av.x, av.y, av.z, av.w, B[ks][0][0], B[ks][0][1]);
                mma_tf32(C[1], av.x, av.y, av.z, av.w, B[ks][1][0], B[ks][1][1]);
            }
            #pragma unroll
            for (int nb = 0; nb < 2; nb++) {
                const int fl = flw + nb * 8 + 2 * c;
                unsigned long long h0 =
                    *(const unsigned long long*)(hq + (t * 4 + qa) * 128 + fl);
                unsigned long long h1 =
                    *(const unsigned long long*)(hq + (t * 4 + qa + 2) * 128 + fl);
                unsigned long long s01 = mul2(selu2(C[nb][0], C[nb][1]), em0p);
                unsigned long long s23 = mul2(selu2(C[nb][2], C[nb][3]), em1p);
                acc2[nb] = fma2(s01, h0, acc2[nb]);
                acc2[nb] = fma2(s23, h1, acc2[nb]);
            }
        }

        if (jt < 7) {
            uint32_t* af1 = afb[buf ^ 1];
            #pragma unroll
            for (int q = 0; q < 4; q++) {
                int idx = tid + q * 256;
                if (idx < 960) {
                    int i_l = idx / 240, rem = idx - i_l * 240;
                    int jj = rem / 15, p = rem - jj * 15;
                    int rr = jj * 4 + i_l;
                    int t = rr >> 4, rloc = rr & 15;
                    int rbit = rloc >> 3, r8 = rloc & 7;
                    int ks = p >> 2, kin = (2 * p) & 7;
                    int c0 = kin & 3, chalf = kin >> 2;
                    int slot = (t * 4 + ks) * 132 + (r8 * 4 + c0) * 4 + (rbit | (chalf << 1));
                    af1[slot]     = f2tf(va[q].x);
                    af1[slot + 4] = f2tf(va[q].y);
                }
            }
            CP_WAIT0();
            __syncthreads();
        }
    }

    #pragma unroll
    for (int nb = 0; nb < 2; nb++) {
        float a0, a1; unpack2(acc2[nb], a0, a1);
        a0 += __shfl_xor_sync(0xffffffffu, a0, 16);
        a1 += __shfl_xor_sync(0xffffffffu, a1, 16);
        if (l < 16) {
            const int f = f0w + nb * 8 + 2 * c;
            *(float2*)(g_h1 + (size_t)(b * NA + i0 + r) * HD + f) = make_float2(a0, a1);
        }
    }
}

// =========================================================================
// Kernel 2 (R14 tile, LOG2E unfolded from staging): out = selu(z@Ww^T+bw)*nm+h
// M=2048, K=512, N=256. Grid 256 = 64 rb x 4 fb; CTA = 32 rows x 64 f.
// LDG-early/STS-late double-buffered K-chunks of 64. Fragment-order smem.
// Ww staged raw rna tf32 (no LOG2E mul: -128 FMUL/thread); epilogue
// multiplies accumulators by LOG2E once (8 FMUL/thread) before selu_l2.
// =========================================================================
#define K2_ZW (16 * 132)
#define K2_WW (8 * 516)
#define K2_SMEM ((2*K2_ZW + 2*K2_WW) * 4)

__global__ __launch_bounds__(256) void efconv_k2(
    const float* __restrict__ hbuf, const float* __restrict__ node_mask,
    const float* __restrict__ Ww, const float* __restrict__ bw,
    float* __restrict__ out)
{
    extern __shared__ uint32_t sm2[];
    uint32_t* zfb[2] = { sm2, sm2 + K2_ZW };
    uint32_t* wfb[2] = { sm2 + 2 * K2_ZW, sm2 + 2 * K2_ZW + K2_WW };

    const int tid = threadIdx.x;
    const int w = tid >> 5, l = tid & 31;
    const int r = l >> 2, c = l & 3;
    const int rb = blockIdx.x >> 2, fb = blockIdx.x & 3;
    const int row0 = rb * 32;
    const int rt = w & 1, fh = w >> 1;

    float C[2][4];
    #pragma unroll
    for (int nb = 0; nb < 2; nb++) {
        float2 bv = *(const float2*)(bw + fb * 64 + fh * 16 + nb * 8 + 2 * c);
        C[nb][0] = bv.x; C[nb][1] = bv.y;
        C[nb][2] = bv.x; C[nb][3] = bv.y;
    }

    // ---- prologue: stage kc = 0 ----
    {
        #pragma unroll
        for (int q = 0; q < 2; q++) {
            int idx = tid + q * 256;
            int rr = idx >> 4, kq = idx & 15;
            float4 v = *(const float4*)(hbuf + (size_t)(row0 + rr) * HD + kq * 4);
            int rt2 = rr >> 4, rloc = rr & 15;
            int rbit = rloc >> 3, r8 = rloc & 7;
            int ks = kq >> 1, chalf = kq & 1;
            uint32_t* d = zfb[0] + (rt2 * 8 + ks) * 132 + r8 * 16 + (rbit | (chalf << 1));
            d[0] = f2tf(v.x); d[4] = f2tf(v.y);
            d[8] = f2tf(v.z); d[12] = f2tf(v.w);
        }
        #pragma unroll
        for (int q = 0; q < 4; q++) {
            int idx = tid + q * 256;
            int ff = idx >> 4, kq = idx & 15;
            float4 v = *(const float4*)(Ww + (size_t)(fb * 64 + ff) * (2 * HD) + kq * 4);
            int ks = kq >> 1, half = kq & 1;
            uint32_t* d = wfb[0] + ks * 516 + ff * 8 + half;
            d[0] = f2tf(v.x); d[2] = f2tf(v.y);
            d[4] = f2tf(v.z); d[6] = f2tf(v.w);
        }
    }
    __syncthreads();

    #pragma unroll 1
    for (int kc = 0; kc < 8; kc++) {
        const int buf = kc & 1;

        // ---- prefetch stage kc+1 (LDG only) ----
        float4 zv[2], wv[4];
        if (kc < 7) {
            const float* zsrc = (kc + 1 < 4) ? hbuf : g_h1;
            const int cb = ((kc + 1) & 3) * 64;
            #pragma unroll
            for (int q = 0; q < 2; q++) {
                int idx = tid + q * 256;
                int rr = idx >> 4, kq = idx & 15;
                zv[q] = *(const float4*)(zsrc + (size_t)(row0 + rr) * HD + cb + kq * 4);
            }
            #pragma unroll
            for (int q = 0; q < 4; q++) {
                int idx = tid + q * 256;
                int ff = idx >> 4, kq = idx & 15;
                wv[q] = *(const float4*)(
                    Ww + (size_t)(fb * 64 + ff) * (2 * HD) + (kc + 1) * 64 + kq * 4);
            }
        }

        // ---- compute stage kc ----
        const uint32_t* zf = zfb[buf];
        const uint32_t* wf = wfb[buf];
        #pragma unroll
        for (int ks = 0; ks < 8; ks++) {
            uint4 av = *(const uint4*)(zf + (rt * 8 + ks) * 132 + l * 4);
            #pragma unroll
            for (int nb = 0; nb < 2; nb++) {
                const int fl = fh * 16 + nb * 8 + r;
                uint2 bb = *(const uint2*)(wf + ks * 516 + fl * 8 + c * 2);
                mma_tf32(C[nb], av.x, av.y, av.z, av.w, bb.x, bb.y);
            }
        }

        // ---- STS stage kc+1 + barrier ----
        if (kc < 7) {
            uint32_t* zf1 = zfb[buf ^ 1];
            uint32_t* wf1 = wfb[buf ^ 1];
            #pragma unroll
            for (int q = 0; q < 2; q++) {
                int idx = tid + q * 256;
                int rr = idx >> 4, kq = idx & 15;
                int rt2 = rr >> 4, rloc = rr & 15;
                int rbit = rloc >> 3, r8 = rloc & 7;
                int ks = kq >> 1, chalf = kq & 1;
                uint32_t* d = zf1 + (rt2 * 8 + ks) * 132 + r8 * 16 + (rbit | (chalf << 1));
                d[0] = f2tf(zv[q].x); d[4] = f2tf(zv[q].y);
                d[8] = f2tf(zv[q].z); d[12] = f2tf(zv[q].w);
            }
            #pragma unroll
            for (int q = 0; q < 4; q++) {
                int idx = tid + q * 256;
                int ff = idx >> 4, kq = idx & 15;
                int ks = kq >> 1, half = kq & 1;
                uint32_t* d = wf1 + ks * 516 + ff * 8 + half;
                d[0] = f2tf(wv[q].x); d[2] = f2tf(wv[q].y);
                d[4] = f2tf(wv[q].z); d[6] = f2tf(wv[q].w);
            }
            __syncthreads();
        }
    }

    // ---- epilogue: selu(D) * nm + h  (x LOG2E applied here, once) ----
    const int rg0 = row0 + rt * 16 + r, rg1 = rg0 + 8;
    const float nm0 = node_mask[rg0], nm1 = node_mask[rg1];
    #pragma unroll
    for (int nb = 0; nb < 2; nb++) {
        int f = fb * 64 + fh * 16 + nb * 8 + 2 * c;
        float2 h0 = *(const float2*)(hbuf + (size_t)rg0 * HD + f);
        float2 h1 = *(const float2*)(hbuf + (size_t)rg1 * HD + f);
        float2 o0, o1;
        o0.x = selu_l2(C[nb][0] * LOG2E) * nm0 + h0.x;
        o0.y = selu_l2(C[nb][1] * LOG2E) * nm0 + h0.y;
        o1.x = selu_l2(C[nb][2] * LOG2E) * nm1 + h1.x;
        o1.y = selu_l2(C[nb][3] * LOG2E) * nm1 + h1.y;
        *(float2*)(out + (size_t)rg0 * HD + f) = o0;
        *(float2*)(out + (size_t)rg1 * HD + f) = o1;
    }
}

extern "C" void kernel_launch(void* const* d_in, const int* in_sizes, int n_in,
                              void* d_out, int out_size)
{
    const float* h   = (const float*)d_in[0];   // (16,128,256)
    const float* e   = (const float*)d_in[1];   // (16,128,128,30)
    const float* nm  = (const float*)d_in[2];   // (16,128,1)
    const float* em  = (const float*)d_in[3];   // (16,128,128,1)
    const float* Wf  = (const float*)d_in[4];   // (256,30)
    const float* bf  = (const float*)d_in[5];   // (256,)
    const float* Ww  = (const float*)d_in[6];   // (256,512)
    const float* bw  = (const float*)d_in[7];   // (256,)
    float* out = (float*)d_out;                  // (16,128,256)

    cudaFuncSetAttribute(efconv_k2, cudaFuncAttributeMaxDynamicSharedMemorySize, K2_SMEM);

    efconv_k1<<<1024, 256>>>(h, e, em, Wf, bf);
    efconv_k2<<<256, 256, K2_SMEM>>>(h, nm, Ww, bw, out);
}

// round 17
// speedup vs baseline: 1.1395x; 1.0331x over previous
#include <cuda_runtime.h>
#include <cstdint>

#define NBATCH 16
#define NA 128
#define HD 256
#define EF 30

#define SELU_SCALE 1.0507009873554805f
#define SELU_SA    1.7580993408473766f     // scale * alpha
#define LOG2E      1.4426950408889634f
#define SLN2       (1.0507009873554805f * 0.69314718055994531f)  // scale*ln2
#define SA_H2      0x3F083F08u             // f16x2 {1.7578125, 1.7578125}
#define NSA_H2     0xBF08BF08u             // f16x2 {-1.7578125, -1.7578125}

// intermediate h1 (16*128*256 fp32 = 2 MB)
__device__ float g_h1[NBATCH * NA * HD];

__device__ __forceinline__ uint32_t f2tf(float x) {
    uint32_t u; asm("cvt.rna.tf32.f32 %0, %1;" : "=r"(u) : "f"(x)); return u;
}
__device__ __forceinline__ float ex2f(float x) {
    float y; asm("ex2.approx.f32 %0, %1;" : "=f"(y) : "f"(x)); return y;
}
// scalar selu on d2 = d*log2e (for k2 epilogue)
__device__ __forceinline__ float selu_l2(float d2) {
    float e = ex2f(d2);
    return fmaf(SLN2, fmaxf(d2, 0.f), fminf(fmaf(SELU_SA, e, -SELU_SA), 0.f));
}
__device__ __forceinline__ unsigned long long pack2(float a, float b) {
    unsigned long long v;
    asm("mov.b64 %0, {%1, %2};" : "=l"(v) : "f"(a), "f"(b));
    return v;
}
__device__ __forceinline__ unsigned long long mul2(unsigned long long a,
                                                   unsigned long long b) {
    unsigned long long d;
    asm("mul.rn.f32x2 %0, %1, %2;" : "=l"(d) : "l"(a), "l"(b));
    return d;
}
__device__ __forceinline__ unsigned long long fma2(unsigned long long a,
                                                   unsigned long long b,
                                                   unsigned long long c) {
    unsigned long long d;
    asm("fma.rn.f32x2 %0, %1, %2, %3;" : "=l"(d) : "l"(a), "l"(b), "l"(c));
    return d;
}
__device__ __forceinline__ void unpack2(unsigned long long v, float& a, float& b) {
    asm("mov.b64 {%0, %1}, %2;" : "=f"(a), "=f"(b) : "l"(v));
}
// packed selu pair on (c0,c1) = d*log2e -> f32x2 {selu(d0), selu(d1)}
__device__ __forceinline__ unsigned long long selu2(float c0, float c1) {
    uint32_t h2, e2, f2, n2;
    asm("cvt.rn.f16x2.f32 %0, %1, %2;" : "=r"(h2) : "f"(c1), "f"(c0)); // lo=c0
    asm("ex2.approx.f16x2 %0, %1;" : "=r"(e2) : "r"(h2));
    asm("fma.rn.f16x2 %0, %1, %2, %3;"
        : "=r"(f2) : "r"(e2), "r"(SA_H2), "r"(NSA_H2));
    asm("min.f16x2 %0, %1, %2;" : "=r"(n2) : "r"(f2), "r"(0u));
    float n0, n1;
    asm("{ .reg .b16 lo, hi;\n\t"
        "mov.b32 {lo, hi}, %2;\n\t"
        "cvt.f32.f16 %0, lo;\n\t"
        "cvt.f32.f16 %1, hi; }"
        : "=f"(n0), "=f"(n1) : "r"(n2));
    float s0 = fmaf(SLN2, fmaxf(c0, 0.f), n0);
    float s1 = fmaf(SLN2, fmaxf(c1, 0.f), n1);
    return pack2(s0, s1);
}
__device__ __forceinline__ void mma_tf32(float c[4],
                                         uint32_t a0, uint32_t a1, uint32_t a2, uint32_t a3,
                                         uint32_t b0, uint32_t b1) {
    asm volatile(
        "mma.sync.aligned.m16n8k8.row.col.f32.tf32.tf32.f32 "
        "{%0,%1,%2,%3}, {%4,%5,%6,%7}, {%8,%9}, {%0,%1,%2,%3};"
        : "+f"(c[0]), "+f"(c[1]), "+f"(c[2]), "+f"(c[3])
        : "r"(a0), "r"(a1), "r"(a2), "r"(a3), "r"(b0), "r"(b1));
}
__device__ __forceinline__ uint32_t smem_u32(const void* p) {
    return (uint32_t)__cvta_generic_to_shared(p);
}
#define CP_ASYNC16(dst_u32, src) \
    asm volatile("cp.async.ca.shared.global [%0], [%1], 16;" \
                 :: "r"(dst_u32), "l"(src))
#define CP_COMMIT() asm volatile("cp.async.commit_group;" ::: "memory")
#define CP_WAIT0()  asm volatile("cp.async.wait_group 0;" ::: "memory")

// =========================================================================
// Kernel 1: CTA = (b, i-tile of 4, f-half). grid = 1024, lb(256,3).
// Staging index math HOISTED: per-thread slot/offset precomputed once;
// per-stage address = base + jt*480 floats. Double-buffered; cp.async h;
// fragment-order A; packed f16x2 selu epilogue; lane-pair fold.
// =========================================================================
#define EMS 132
#define K1_AFW (16 * 132)
#define K1_HW  (16 * 128)

__global__ __launch_bounds__(256, 3) void efconv_k1(
    const float* __restrict__ hbuf, const float* __restrict__ e,
    const float* __restrict__ edge_mask, const float* __restrict__ Wf,
    const float* __restrict__ bf)
{
    __shared__ uint32_t afb[2][K1_AFW];
    __shared__ float    hqb[2][K1_HW];
    __shared__ float    em_s[4 * EMS];

    const int tid = threadIdx.x;
    const int w = tid >> 5, l = tid & 31;
    const int r = l >> 2, c = l & 3;
    const int bid = blockIdx.x;
    const int fh = bid & 1, it = (bid >> 1) & 31, b = bid >> 6;
    const int i0 = it * 4;
    const int f0w = fh * 128 + w * 16;
    const int flw = w * 16;

    const int h_jj0 = tid >> 5, h_fq0 = tid & 31;
    const int h_jj1 = (tid + 256) >> 5, h_fq1 = tid & 31;
    // cp.async fixed src/dst (advance src by 16*HD per jt)
    const float* hsrc0 = hbuf + (size_t)(b * NA + h_jj0) * HD + fh * 128 + h_fq0 * 4;
    const float* hsrc1 = hbuf + (size_t)(b * NA + h_jj1) * HD + fh * 128 + h_fq1 * 4;
    const uint32_t hdst0 = h_jj0 * 128 + h_fq0 * 4;
    const uint32_t hdst1 = h_jj1 * 128 + h_fq1 * 4;

    // ---- hoisted staging descriptors: slot + gmem base offset per q ----
    int st_slot[4], st_off[4];
    #pragma unroll
    for (int q = 0; q < 4; q++) {
        int idx = tid + q * 256;
        int il = min(idx, 959) / 240;            // clamp keeps math in-range
        int rem = min(idx, 959) - il * 240;
        int jj = rem / 15, p = rem - jj * 15;
        st_off[q] = ((b * NA + i0 + il) * NA + jj) * EF + 2 * p;
        int rr = jj * 4 + il;
        int t = rr >> 4, rloc = rr & 15;
        int rbit = rloc >> 3, r8 = rloc & 7;
        int ks = p >> 2, kin = (2 * p) & 7;
        int c0 = kin & 3, chalf = kin >> 2;
        st_slot[q] = (t * 4 + ks) * 132 + (r8 * 4 + c0) * 4 + (rbit | (chalf << 1));
    }
    const bool v3 = (tid < 192);   // q=3 validity (q<3 always valid)

    // ---- preload Wf fragments (x log2e, rna) + bias pairs (x log2e) ----
    uint32_t B[4][2][2];
    float2 bfv[2];
    #pragma unroll
    for (int nb = 0; nb < 2; nb++) {
        const int fr = f0w + nb * 8 + r;
        #pragma unroll
        for (int ks = 0; ks < 4; ks++) {
            int k0 = ks * 8 + c, k1 = k0 + 4;
            B[ks][nb][0] = f2tf(Wf[fr * EF + k0] * LOG2E);
            B[ks][nb][1] = (k1 < EF) ? f2tf(Wf[fr * EF + k1] * LOG2E) : 0u;
        }
        float2 bv = *(const float2*)(bf + f0w + nb * 8 + 2 * c);
        bfv[nb] = make_float2(bv.x * LOG2E, bv.y * LOG2E);
    }

    // ---- em[b, i0:i0+4, :] once ----
    #pragma unroll
    for (int q = 0; q < 2; q++) {
        int idx = tid + q * 256;
        int i_l = idx >> 7, j = idx & 127;
        em_s[i_l * EMS + j] = edge_mask[((b * NA) + i0 + i_l) * NA + j];
    }
    // ---- zero k=30,31 fragment slots (both buffers) ----
    if (tid < 64) {
        int rr = tid, t = rr >> 4, rloc = rr & 15;
        int rbit = rloc >> 3, r8 = rloc & 7;
        int base = (t * 4 + 3) * 132 + r8 * 16;
        #pragma unroll
        for (int bu = 0; bu < 2; bu++) {
            afb[bu][base + 2 * 4 + (rbit | 2)] = 0u;
            afb[bu][base + 3 * 4 + (rbit | 2)] = 0u;
        }
    }

    // ---- prologue: stage jt = 0 ----
    {
        CP_ASYNC16(smem_u32(hqb[0]) + hdst0 * 4, hsrc0);
        CP_ASYNC16(smem_u32(hqb[0]) + hdst1 * 4, hsrc1);
        CP_COMMIT();
        #pragma unroll
        for (int q = 0; q < 4; q++) {
            if (q < 3 || v3) {
                float2 v = *(const float2*)(e + st_off[q]);
                afb[0][st_slot[q]]     = f2tf(v.x);
                afb[0][st_slot[q] + 4] = f2tf(v.y);
            }
        }
        CP_WAIT0();
    }
    __syncthreads();

    unsigned long long acc2[2] = {};

    #pragma unroll 1
    for (int jt = 0; jt < 8; jt++) {
        const int buf = jt & 1;

        // ---- issue next stage: h via cp.async, e LDG prefetch (hoisted) ----
        float2 va[4];
        if (jt < 7) {
            const int joff = (jt + 1) * 16 * EF;     // +480 floats per stage
            const size_t hoff = (size_t)(jt + 1) * 16 * HD;
            CP_ASYNC16(smem_u32(hqb[buf ^ 1]) + hdst0 * 4, hsrc0 + hoff);
            CP_ASYNC16(smem_u32(hqb[buf ^ 1]) + hdst1 * 4, hsrc1 + hoff);
            CP_COMMIT();
            #pragma unroll
            for (int q = 0; q < 4; q++)
                if (q < 3 || v3)
                    va[q] = *(const float2*)(e + st_off[q] + joff);
        }

        const uint32_t* af = afb[buf];
        const float*    hq = hqb[buf];

        // ---- compute stage jt ----
        #pragma unroll
        for (int t = 0; t < 4; t++) {
            const int qa = r >> 2;
            const float em0 = em_s[(r & 3) * EMS + jt * 16 + t * 4 + qa];
            const float em1 = em_s[(r & 3) * EMS + jt * 16 + t * 4 + qa + 2];
            const unsigned long long em0p = pack2(em0, em0);
            const unsigned long long em1p = pack2(em1, em1);
            float C[2][4];
            #pragma unroll
            for (int nb = 0; nb < 2; nb++) {
                C[nb][0] = bfv[nb].x; C[nb][1] = bfv[nb].y;
                C[nb][2] = bfv[nb].x; C[nb][3] = bfv[nb].y;
            }
            #pragma unroll
            for (int ks = 0; ks < 4; ks++) {
                uint4 av = *(const uint4*)(af + (t * 4 + ks) * 132 + l * 4);
                mma_tf32(C[0], av.x, av.y, av.z, av.w, B[ks][0][0], B[ks][0][1]);
                mma_tf32(C[1], av.x, av.y, av.z, av.w, B[ks][1][0], B[ks][1][1]);
            }
            #pragma unroll
            for (int nb = 0; nb < 2; nb++) {
                const int fl = flw + nb * 8 + 2 * c;
                unsigned long long h0 =
                    *(const unsigned long long*)(hq + (t * 4 + qa) * 128 + fl);
                unsigned long long h1 =
                    *(const unsigned long long*)(hq + (t * 4 + qa + 2) * 128 + fl);
                unsigned long long s01 = mul2(selu2(C[nb][0], C[nb][1]), em0p);
                unsigned long long s23 = mul2(selu2(C[nb][2], C[nb][3]), em1p);
                acc2[nb] = fma2(s01, h0, acc2[nb]);
                acc2[nb] = fma2(s23, h1, acc2[nb]);
            }
        }

        // ---- STS e frags for stage jt+1 (hoisted slots), wait, barrier ----
        if (jt < 7) {
            uint32_t* af1 = afb[buf ^ 1];
            #pragma unroll
            for (int q = 0; q < 4; q++) {
                if (q < 3 || v3) {
                    af1[st_slot[q]]     = f2tf(va[q].x);
                    af1[st_slot[q] + 4] = f2tf(va[q].y);
                }
            }
            CP_WAIT0();
            __syncthreads();
        }
    }

    // ---- combine lane pairs (l, l^16) and write h1 ----
    #pragma unroll
    for (int nb = 0; nb < 2; nb++) {
        float a0, a1; unpack2(acc2[nb], a0, a1);
        a0 += __shfl_xor_sync(0xffffffffu, a0, 16);
        a1 += __shfl_xor_sync(0xffffffffu, a1, 16);
        if (l < 16) {
            const int f = f0w + nb * 8 + 2 * c;
            *(float2*)(g_h1 + (size_t)(b * NA + i0 + r) * HD + f) = make_float2(a0, a1);
        }
    }
}

// =========================================================================
// Kernel 2: out = selu([h|h1] @ Ww^T + bw) * nm + h
// Grid 256 = 64 rb x 4 fb; CTA = 32 rows x 64 f. Staging index math
// HOISTED (slots + base offsets; per-stage address = base + kc*64).
// LDG-early/STS-late double-buffered. Ww staged raw; LOG2E in epilogue.
// =========================================================================
#define K2_ZW (16 * 132)
#define K2_WW (8 * 516)
#define K2_SMEM ((2*K2_ZW + 2*K2_WW) * 4)

__global__ __launch_bounds__(256) void efconv_k2(
    const float* __restrict__ hbuf, const float* __restrict__ node_mask,
    const float* __restrict__ Ww, const float* __restrict__ bw,
    float* __restrict__ out)
{
    extern __shared__ uint32_t sm2[];
    uint32_t* zfb[2] = { sm2, sm2 + K2_ZW };
    uint32_t* wfb[2] = { sm2 + 2 * K2_ZW, sm2 + 2 * K2_ZW + K2_WW };

    const int tid = threadIdx.x;
    const int w = tid >> 5, l = tid & 31;
    const int r = l >> 2, c = l & 3;
    const int rb = blockIdx.x >> 2, fb = blockIdx.x & 3;
    const int row0 = rb * 32;
    const int rt = w & 1, fh = w >> 1;

    // ---- hoisted staging descriptors ----
    int z_slot[2], z_off[2];
    #pragma unroll
    for (int q = 0; q < 2; q++) {
        int idx = tid + q * 256;
        int rr = idx >> 4, kq = idx & 15;
        z_off[q] = (row0 + rr) * HD + kq * 4;
        int rt2 = rr >> 4, rloc = rr & 15;
        int rbit = rloc >> 3, r8 = rloc & 7;
        int ks = kq >> 1, chalf = kq & 1;
        z_slot[q] = (rt2 * 8 + ks) * 132 + r8 * 16 + (rbit | (chalf << 1));
    }
    int w_slot[4], w_off[4];
    #pragma unroll
    for (int q = 0; q < 4; q++) {
        int idx = tid + q * 256;
        int ff = idx >> 4, kq = idx & 15;
        w_off[q] = (fb * 64 + ff) * (2 * HD) + kq * 4;
        int ks = kq >> 1, half = kq & 1;
        w_slot[q] = ks * 516 + ff * 8 + half;
    }

    float C[2][4];
    #pragma unroll
    for (int nb = 0; nb < 2; nb++) {
        float2 bv = *(const float2*)(bw + fb * 64 + fh * 16 + nb * 8 + 2 * c);
        C[nb][0] = bv.x; C[nb][1] = bv.y;
        C[nb][2] = bv.x; C[nb][3] = bv.y;
    }

    // ---- prologue: stage kc = 0 ----
    {
        #pragma unroll
        for (int q = 0; q < 2; q++) {
            float4 v = *(const float4*)(hbuf + z_off[q]);
            uint32_t* d = zfb[0] + z_slot[q];
            d[0] = f2tf(v.x); d[4] = f2tf(v.y);
            d[8] = f2tf(v.z); d[12] = f2tf(v.w);
        }
        #pragma unroll
        for (int q = 0; q < 4; q++) {
            float4 v = *(const float4*)(Ww + w_off[q]);
            uint32_t* d = wfb[0] + w_slot[q];
            d[0] = f2tf(v.x); d[2] = f2tf(v.y);
            d[4] = f2tf(v.z); d[6] = f2tf(v.w);
        }
    }
    __syncthreads();

    #pragma unroll 1
    for (int kc = 0; kc < 8; kc++) {
        const int buf = kc & 1;

        // ---- prefetch stage kc+1 (LDG only, hoisted addresses) ----
        float4 zv[2], wv[4];
        if (kc < 7) {
            const float* zsrc = (kc + 1 < 4) ? hbuf : g_h1;
            const int cb = ((kc + 1) & 3) * 64;
            #pragma unroll
            for (int q = 0; q < 2; q++)
                zv[q] = *(const float4*)(zsrc + z_off[q] + cb);
            #pragma unroll
            for (int q = 0; q < 4; q++)
                wv[q] = *(const float4*)(Ww + w_off[q] + (kc + 1) * 64);
        }

        // ---- compute stage kc ----
        const uint32_t* zf = zfb[buf];
        const uint32_t* wf = wfb[buf];
        #pragma unroll
        for (int ks = 0; ks < 8; ks++) {
            uint4 av = *(const uint4*)(zf + (rt * 8 + ks) * 132 + l * 4);
            #pragma unroll
            for (int nb = 0; nb < 2; nb++) {
                const int fl = fh * 16 + nb * 8 + r;
                uint2 bb = *(const uint2*)(wf + ks * 516 + fl * 8 + c * 2);
                mma_tf32(C[nb], av.x, av.y, av.z, av.w, bb.x, bb.y);
            }
        }

        // ---- STS stage kc+1 + barrier ----
        if (kc < 7) {
            uint32_t* zf1 = zfb[buf ^ 1];
            uint32_t* wf1 = wfb[buf ^ 1];
            #pragma unroll
            for (int q = 0; q < 2; q++) {
                uint32_t* d = zf1 + z_slot[q];
                d[0] = f2tf(zv[q].x); d[4] = f2tf(zv[q].y);
                d[8] = f2tf(zv[q].z); d[12] = f2tf(zv[q].w);
            }
            #pragma unroll
            for (int q = 0; q < 4; q++) {
                uint32_t* d = wf1 + w_slot[q];
                d[0] = f2tf(wv[q].x); d[2] = f2tf(wv[q].y);
                d[4] = f2tf(wv[q].z); d[6] = f2tf(wv[q].w);
            }
            __syncthreads();
        }
    }

    // ---- epilogue: selu(D) * nm + h  (x LOG2E applied here, once) ----
    const int rg0 = row0 + rt * 16 + r, rg1 = rg0 + 8;
    const float nm0 = node_mask[rg0], nm1 = node_mask[rg1];
    #pragma unroll
    for (int nb = 0; nb < 2; nb++) {
        int f = fb * 64 + fh * 16 + nb * 8 + 2 * c;
        float2 h0 = *(const float2*)(hbuf + (size_t)rg0 * HD + f);
        float2 h1 = *(const float2*)(hbuf + (size_t)rg1 * HD + f);
        float2 o0, o1;
        o0.x = selu_l2(C[nb][0] * LOG2E) * nm0 + h0.x;
        o0.y = selu_l2(C[nb][1] * LOG2E) * nm0 + h0.y;
        o1.x = selu_l2(C[nb][2] * LOG2E) * nm1 + h1.x;
        o1.y = selu_l2(C[nb][3] * LOG2E) * nm1 + h1.y;
        *(float2*)(out + (size_t)rg0 * HD + f) = o0;
        *(float2*)(out + (size_t)rg1 * HD + f) = o1;
    }
}

extern "C" void kernel_launch(void* const* d_in, const int* in_sizes, int n_in,
                              void* d_out, int out_size)
{
    const float* h   = (const float*)d_in[0];   // (16,128,256)
    const float* e   = (const float*)d_in[1];   // (16,128,128,30)
    const float* nm  = (const float*)d_in[2];   // (16,128,1)
    const float* em  = (const float*)d_in[3];   // (16,128,128,1)
    const float* Wf  = (const float*)d_in[4];   // (256,30)
    const float* bf  = (const float*)d_in[5];   // (256,)
    const float* Ww  = (const float*)d_in[6];   // (256,512)
    const float* bw  = (const float*)d_in[7];   // (256,)
    float* out = (float*)d_out;                  // (16,128,256)

    cudaFuncSetAttribute(efconv_k2, cudaFuncAttributeMaxDynamicSharedMemorySize, K2_SMEM);

    efconv_k1<<<1024, 256>>>(h, e, em, Wf, bf);
    efconv_k2<<<256, 256, K2_SMEM>>>(h, nm, Ww, bw, out);
}